// round 2
// baseline (speedup 1.0000x reference)
#include <cuda_runtime.h>

namespace {
constexpr int NTHREADS = 256;
constexpr int TILE    = 32;
constexpr int STRIDE  = TILE + 1;          // pad to avoid bank conflicts
constexpr int NCOEF   = 316;               // 32*1 + 24*3 + 20*5 + 16*7
constexpr int NPAIR   = 1174;              // 528 + 300 + 210 + 136
constexpr int NRAD    = 64;
constexpr int NSP     = 4;
constexpr int NFEAT   = NPAIR + NRAD + 1;  // 1239
constexpr int NSLOTS  = (NFEAT + NTHREADS - 1) / NTHREADS;  // 5
constexpr int MAXS    = 1024;
}

__device__ int g_start[MAXS + 1];

// structure_index is sorted: fill g_start[s] = first atom of structure s.
__global__ void bounds_kernel(const int* __restrict__ sidx, int n_atoms, int S) {
    int i = blockIdx.x * blockDim.x + threadIdx.x;
    if (i >= n_atoms) return;
    int s  = sidx[i];
    int sp = (i == 0) ? -1 : sidx[i - 1];
    for (int t = sp + 1; t <= s && t <= MAXS; ++t) g_start[t] = i;
    if (i == n_atoms - 1)
        for (int t = s + 1; t <= S && t <= MAXS; ++t) g_start[t] = n_atoms;
}

// Accumulate pair invariant sum_j (-1)^j A[p1,j]*A[p2,D-1-j] over a tile of
// atoms into 4 per-species register accumulators (scale applied at the end).
template<int D>
__device__ __forceinline__ void accum_pairs(const float* __restrict__ r1,
                                            const float* __restrict__ r2,
                                            const int* __restrict__ ssp, int nt,
                                            float (&acc)[NSP]) {
    for (int ta = 0; ta < nt; ++ta) {
        float v = 0.f;
#pragma unroll
        for (int j = 0; j < D; ++j) {
            float t = r1[j * STRIDE + ta] * r2[(D - 1 - j) * STRIDE + ta];
            v = (j & 1) ? (v - t) : (v + t);
        }
        int sp = ssp[ta];
        acc[0] += (sp == 0) ? v : 0.f;
        acc[1] += (sp == 1) ? v : 0.f;
        acc[2] += (sp == 2) ? v : 0.f;
        acc[3] += (sp == 3) ? v : 0.f;
    }
}

__global__ __launch_bounds__(NTHREADS)
void le_ace_kernel(const float* __restrict__ comp,
                   const float* __restrict__ radial,
                   const float* __restrict__ sph0,
                   const float* __restrict__ sph1,
                   const float* __restrict__ sph2,
                   const float* __restrict__ sph3,
                   const int* __restrict__ species,
                   float* __restrict__ out,
                   int n_atoms) {
    __shared__ float tileS[NCOEF * STRIDE];   // [coeff][atom-in-tile]
    __shared__ int   ssp[TILE];

    const int tid = threadIdx.x;
    const int s   = blockIdx.x;

    // ---- per-thread feature-slot metadata (registers only) ----
    int   sc1[NSLOTS], sc2[NSLOTS], sdv[NSLOTS];
    float ssc[NSLOTS];
    float facc[NSLOTS][NSP];
#pragma unroll
    for (int k = 0; k < NSLOTS; ++k) {
        int f = tid + k * NTHREADS;
        sc1[k] = 0; sc2[k] = 0; sdv[k] = 0; ssc[k] = 1.f;
#pragma unroll
        for (int sp = 0; sp < NSP; ++sp) facc[k][sp] = 0.f;
        if (f < NPAIR) {
            int l, q, base, coff;
            if (f < 528)       { l = 0; q = 32; base = 0;    coff = 0;   }
            else if (f < 828)  { l = 1; q = 24; base = 528;  coff = 32;  }
            else if (f < 1038) { l = 2; q = 20; base = 828;  coff = 104; }
            else               { l = 3; q = 16; base = 1038; coff = 204; }
            int rem = f - base, i1 = 0;
            while (rem >= q - i1) { rem -= q - i1; ++i1; }   // triangular inversion
            int i2 = i1 + rem;
            int d  = 2 * l + 1;
            sc1[k] = coff + i1 * d;
            sc2[k] = coff + i2 * d;
            sdv[k] = d;
            const float invsq[4] = {1.0f, 0.5773502691896258f,
                                    0.4472135954999579f, 0.3779644730092272f};
            ssc[k] = invsq[l] * ((i1 == i2) ? 1.0f : 1.4142135623730951f);
        }
    }

    const int a0 = g_start[s];
    const int a1 = g_start[s + 1];

    for (int base = a0; base < a1; base += TILE) {
        const int nt = min(TILE, a1 - base);
        __syncthreads();   // previous tile's compute done before overwriting tileS
        // stage coefficient tile: coalesced along atoms for each coeff row
        for (int idx = tid; idx < NCOEF * TILE; idx += NTHREADS) {
            int c  = idx >> 5;
            int ta = idx & (TILE - 1);
            if (ta < nt) {
                const float* p; int r;
                if (c < 32)       { p = sph0; r = c;       }
                else if (c < 104) { p = sph1; r = c - 32;  }
                else if (c < 204) { p = sph2; r = c - 104; }
                else              { p = sph3; r = c - 204; }
                tileS[c * STRIDE + ta] = p[(long)r * n_atoms + base + ta];
            }
        }
        if (tid < TILE) ssp[tid] = (tid < nt) ? species[base + tid] : 0;
        __syncthreads();

#pragma unroll
        for (int k = 0; k < NSLOTS; ++k) {
            int f = tid + k * NTHREADS;
            if (f < NPAIR) {
                const float* r1 = tileS + sc1[k] * STRIDE;
                const float* r2 = tileS + sc2[k] * STRIDE;
                switch (sdv[k]) {
                    case 1:  accum_pairs<1>(r1, r2, ssp, nt, facc[k]); break;
                    case 3:  accum_pairs<3>(r1, r2, ssp, nt, facc[k]); break;
                    case 5:  accum_pairs<5>(r1, r2, ssp, nt, facc[k]); break;
                    default: accum_pairs<7>(r1, r2, ssp, nt, facc[k]); break;
                }
            } else if (f < NPAIR + NRAD) {
                int j = f - NPAIR;
                for (int ta = 0; ta < nt; ++ta) {
                    float v = radial[(long)(base + ta) * NRAD + j];
                    int sp = ssp[ta];
                    facc[k][0] += (sp == 0) ? v : 0.f;
                    facc[k][1] += (sp == 1) ? v : 0.f;
                    facc[k][2] += (sp == 2) ? v : 0.f;
                    facc[k][3] += (sp == 3) ? v : 0.f;
                }
            } else if (f == NPAIR + NRAD) {
                for (int ta = 0; ta < nt; ++ta) {
                    float v = comp[base + ta];
                    int sp = ssp[ta];
                    facc[k][0] += (sp == 0) ? v : 0.f;
                    facc[k][1] += (sp == 1) ? v : 0.f;
                    facc[k][2] += (sp == 2) ? v : 0.f;
                    facc[k][3] += (sp == 3) ? v : 0.f;
                }
            }
        }
    }

    // ---- write: each (feature, species) owned by exactly one thread ----
    const int ncols = NSP * NFEAT;   // 4956
#pragma unroll
    for (int k = 0; k < NSLOTS; ++k) {
        int f = tid + k * NTHREADS;
        if (f >= NFEAT) continue;
#pragma unroll
        for (int sp = 0; sp < NSP; ++sp) {
            int col;
            if (f < NPAIR)             col = NSP + NSP * NRAD + sp * NPAIR + f;  // B2 block
            else if (f < NPAIR + NRAD) col = NSP + sp * NRAD + (f - NPAIR);      // radial block
            else                       col = sp;                                 // composition
            out[s * ncols + col] = ssc[k] * facc[k][sp];
        }
    }
}

extern "C" void kernel_launch(void* const* d_in, const int* in_sizes, int n_in,
                              void* d_out, int out_size) {
    const float* comp    = (const float*)d_in[0];
    const float* radial  = (const float*)d_in[1];
    const float* sph0    = (const float*)d_in[2];
    const float* sph1    = (const float*)d_in[3];
    const float* sph2    = (const float*)d_in[4];
    const float* sph3    = (const float*)d_in[5];
    const int*   sidx    = (const int*)d_in[6];
    const int*   species = (const int*)d_in[7];
    float*       out     = (float*)d_out;

    int n_atoms = in_sizes[0];                 // composition_features is [n_atoms, 1]
    int S       = out_size / (NSP * NFEAT);    // 4956 cols per structure
    if (S > MAXS) S = MAXS;

    bounds_kernel<<<(n_atoms + 255) / 256, 256>>>(sidx, n_atoms, S);
    le_ace_kernel<<<S, NTHREADS>>>(comp, radial, sph0, sph1, sph2, sph3,
                                   species, out, n_atoms);
}

// round 3
// speedup vs baseline: 1.0038x; 1.0038x over previous
#include <cuda_runtime.h>

namespace {
constexpr int NTHREADS = 256;
constexpr int TILE    = 32;
constexpr int STRIDE  = TILE + 1;          // pad to avoid bank conflicts
constexpr int NCOEF   = 316;               // 32*1 + 24*3 + 20*5 + 16*7
constexpr int NPAIR   = 1174;              // 528 + 300 + 210 + 136
constexpr int NRAD    = 64;
constexpr int NSP     = 4;
constexpr int NFEAT   = NPAIR + NRAD + 1;  // 1239
constexpr int NSLOTS  = (NFEAT + NTHREADS - 1) / NTHREADS;  // 5
constexpr int MAXS    = 1024;
}

__device__ int g_start[MAXS + 1];

// structure_index is sorted: fill g_start[s] = first atom of structure s.
__global__ void bounds_kernel(const int* __restrict__ sidx, int n_atoms, int S) {
    int i = blockIdx.x * blockDim.x + threadIdx.x;
    if (i >= n_atoms) return;
    int s  = sidx[i];
    int sp = (i == 0) ? -1 : sidx[i - 1];
    for (int t = sp + 1; t <= s && t <= MAXS; ++t) g_start[t] = i;
    if (i == n_atoms - 1)
        for (int t = s + 1; t <= S && t <= MAXS; ++t) g_start[t] = n_atoms;
}

// Accumulate pair invariant sum_j (-1)^j A[p1,j]*A[p2,D-1-j] over a tile of
// atoms into 4 per-species register accumulators (scale applied at the end).
template<int D>
__device__ __forceinline__ void accum_pairs(const float* __restrict__ r1,
                                            const float* __restrict__ r2,
                                            const int* __restrict__ ssp, int nt,
                                            float (&acc)[NSP]) {
    for (int ta = 0; ta < nt; ++ta) {
        float v = 0.f;
#pragma unroll
        for (int j = 0; j < D; ++j) {
            float t = r1[j * STRIDE + ta] * r2[(D - 1 - j) * STRIDE + ta];
            v = (j & 1) ? (v - t) : (v + t);
        }
        int sp = ssp[ta];
        acc[0] += (sp == 0) ? v : 0.f;
        acc[1] += (sp == 1) ? v : 0.f;
        acc[2] += (sp == 2) ? v : 0.f;
        acc[3] += (sp == 3) ? v : 0.f;
    }
}

__global__ __launch_bounds__(NTHREADS)
void le_ace_kernel(const float* __restrict__ comp,
                   const float* __restrict__ radial,
                   const float* __restrict__ sph0,
                   const float* __restrict__ sph1,
                   const float* __restrict__ sph2,
                   const float* __restrict__ sph3,
                   const int* __restrict__ species,
                   float* __restrict__ out,
                   int n_atoms) {
    __shared__ float tileS[NCOEF * STRIDE];   // [coeff][atom-in-tile]
    __shared__ int   ssp[TILE];

    const int tid = threadIdx.x;
    const int s   = blockIdx.x;

    // ---- per-thread feature-slot metadata (registers only) ----
    int   sc1[NSLOTS], sc2[NSLOTS], sdv[NSLOTS];
    float ssc[NSLOTS];
    float facc[NSLOTS][NSP];
#pragma unroll
    for (int k = 0; k < NSLOTS; ++k) {
        int f = tid + k * NTHREADS;
        sc1[k] = 0; sc2[k] = 0; sdv[k] = 0; ssc[k] = 1.f;
#pragma unroll
        for (int sp = 0; sp < NSP; ++sp) facc[k][sp] = 0.f;
        if (f < NPAIR) {
            int l, q, base, coff;
            if (f < 528)       { l = 0; q = 32; base = 0;    coff = 0;   }
            else if (f < 828)  { l = 1; q = 24; base = 528;  coff = 32;  }
            else if (f < 1038) { l = 2; q = 20; base = 828;  coff = 104; }
            else               { l = 3; q = 16; base = 1038; coff = 204; }
            int rem = f - base, i1 = 0;
            while (rem >= q - i1) { rem -= q - i1; ++i1; }   // triangular inversion
            int i2 = i1 + rem;
            int d  = 2 * l + 1;
            sc1[k] = coff + i1 * d;
            sc2[k] = coff + i2 * d;
            sdv[k] = d;
            const float invsq[4] = {1.0f, 0.5773502691896258f,
                                    0.4472135954999579f, 0.3779644730092272f};
            ssc[k] = invsq[l] * ((i1 == i2) ? 1.0f : 1.4142135623730951f);
        }
    }

    const int a0 = g_start[s];
    const int a1 = g_start[s + 1];

    for (int base = a0; base < a1; base += TILE) {
        const int nt = min(TILE, a1 - base);
        __syncthreads();   // previous tile's compute done before overwriting tileS
        // stage coefficient tile: coalesced along atoms for each coeff row
        for (int idx = tid; idx < NCOEF * TILE; idx += NTHREADS) {
            int c  = idx >> 5;
            int ta = idx & (TILE - 1);
            if (ta < nt) {
                const float* p; int r;
                if (c < 32)       { p = sph0; r = c;       }
                else if (c < 104) { p = sph1; r = c - 32;  }
                else if (c < 204) { p = sph2; r = c - 104; }
                else              { p = sph3; r = c - 204; }
                tileS[c * STRIDE + ta] = p[(long)r * n_atoms + base + ta];
            }
        }
        if (tid < TILE) ssp[tid] = (tid < nt) ? species[base + tid] : 0;
        __syncthreads();

#pragma unroll
        for (int k = 0; k < NSLOTS; ++k) {
            int f = tid + k * NTHREADS;
            if (f < NPAIR) {
                const float* r1 = tileS + sc1[k] * STRIDE;
                const float* r2 = tileS + sc2[k] * STRIDE;
                switch (sdv[k]) {
                    case 1:  accum_pairs<1>(r1, r2, ssp, nt, facc[k]); break;
                    case 3:  accum_pairs<3>(r1, r2, ssp, nt, facc[k]); break;
                    case 5:  accum_pairs<5>(r1, r2, ssp, nt, facc[k]); break;
                    default: accum_pairs<7>(r1, r2, ssp, nt, facc[k]); break;
                }
            } else if (f < NPAIR + NRAD) {
                int j = f - NPAIR;
                for (int ta = 0; ta < nt; ++ta) {
                    float v = radial[(long)(base + ta) * NRAD + j];
                    int sp = ssp[ta];
                    facc[k][0] += (sp == 0) ? v : 0.f;
                    facc[k][1] += (sp == 1) ? v : 0.f;
                    facc[k][2] += (sp == 2) ? v : 0.f;
                    facc[k][3] += (sp == 3) ? v : 0.f;
                }
            } else if (f == NPAIR + NRAD) {
                for (int ta = 0; ta < nt; ++ta) {
                    float v = comp[base + ta];
                    int sp = ssp[ta];
                    facc[k][0] += (sp == 0) ? v : 0.f;
                    facc[k][1] += (sp == 1) ? v : 0.f;
                    facc[k][2] += (sp == 2) ? v : 0.f;
                    facc[k][3] += (sp == 3) ? v : 0.f;
                }
            }
        }
    }

    // ---- write: each (feature, species) owned by exactly one thread ----
    const int ncols = NSP * NFEAT;   // 4956
#pragma unroll
    for (int k = 0; k < NSLOTS; ++k) {
        int f = tid + k * NTHREADS;
        if (f >= NFEAT) continue;
#pragma unroll
        for (int sp = 0; sp < NSP; ++sp) {
            int col;
            if (f < NPAIR)             col = NSP + NSP * NRAD + sp * NPAIR + f;  // B2 block
            else if (f < NPAIR + NRAD) col = NSP + sp * NRAD + (f - NPAIR);      // radial block
            else                       col = sp;                                 // composition
            out[s * ncols + col] = ssc[k] * facc[k][sp];
        }
    }
}

extern "C" void kernel_launch(void* const* d_in, const int* in_sizes, int n_in,
                              void* d_out, int out_size) {
    const float* comp    = (const float*)d_in[0];
    const float* radial  = (const float*)d_in[1];
    const float* sph0    = (const float*)d_in[2];
    const float* sph1    = (const float*)d_in[3];
    const float* sph2    = (const float*)d_in[4];
    const float* sph3    = (const float*)d_in[5];
    const int*   sidx    = (const int*)d_in[6];
    const int*   species = (const int*)d_in[7];
    float*       out     = (float*)d_out;

    int n_atoms = in_sizes[0];                 // composition_features is [n_atoms, 1]
    int S       = out_size / (NSP * NFEAT);    // 4956 cols per structure
    if (S > MAXS) S = MAXS;

    bounds_kernel<<<(n_atoms + 255) / 256, 256>>>(sidx, n_atoms, S);
    le_ace_kernel<<<S, NTHREADS>>>(comp, radial, sph0, sph1, sph2, sph3,
                                   species, out, n_atoms);
}

// round 4
// speedup vs baseline: 1.0287x; 1.0248x over previous
#include <cuda_runtime.h>

namespace {
constexpr int NTHREADS = 256;
constexpr int TILE    = 32;
constexpr int STRIDE  = TILE + 1;          // pad to avoid bank conflicts
constexpr int NCOEF   = 316;               // 32*1 + 24*3 + 20*5 + 16*7
constexpr int NPAIR   = 1174;              // 528 + 300 + 210 + 136
constexpr int NRAD    = 64;
constexpr int NSP     = 4;
constexpr int NFEAT   = NPAIR + NRAD + 1;  // 1239
constexpr int NSLOTS  = (NFEAT + NTHREADS - 1) / NTHREADS;  // 5
constexpr int MAXS    = 1024;
}

__device__ int g_start[MAXS + 1];

// structure_index is sorted: fill g_start[s] = first atom of structure s.
__global__ void bounds_kernel(const int* __restrict__ sidx, int n_atoms, int S) {
    int i = blockIdx.x * blockDim.x + threadIdx.x;
    if (i >= n_atoms) return;
    int s  = sidx[i];
    int sp = (i == 0) ? -1 : sidx[i - 1];
    for (int t = sp + 1; t <= s && t <= MAXS; ++t) g_start[t] = i;
    if (i == n_atoms - 1)
        for (int t = s + 1; t <= S && t <= MAXS; ++t) g_start[t] = n_atoms;
}

// Accumulate pair invariant sum_j (-1)^j A[p1,j]*A[p2,D-1-j] over a tile of
// atoms into 4 per-species register accumulators (scale applied at the end).
template<int D>
__device__ __forceinline__ void accum_pairs(const float* __restrict__ r1,
                                            const float* __restrict__ r2,
                                            const int* __restrict__ ssp, int nt,
                                            float (&acc)[NSP]) {
    for (int ta = 0; ta < nt; ++ta) {
        float v = 0.f;
#pragma unroll
        for (int j = 0; j < D; ++j) {
            float t = r1[j * STRIDE + ta] * r2[(D - 1 - j) * STRIDE + ta];
            v = (j & 1) ? (v - t) : (v + t);
        }
        int sp = ssp[ta];
        acc[0] += (sp == 0) ? v : 0.f;
        acc[1] += (sp == 1) ? v : 0.f;
        acc[2] += (sp == 2) ? v : 0.f;
        acc[3] += (sp == 3) ? v : 0.f;
    }
}

__global__ __launch_bounds__(NTHREADS)
void le_ace_kernel(const float* __restrict__ comp,
                   const float* __restrict__ radial,
                   const float* __restrict__ sph0,
                   const float* __restrict__ sph1,
                   const float* __restrict__ sph2,
                   const float* __restrict__ sph3,
                   const int* __restrict__ species,
                   float* __restrict__ out,
                   int n_atoms) {
    __shared__ float tileS[NCOEF * STRIDE];   // [coeff][atom-in-tile]
    __shared__ int   ssp[TILE];

    const int tid = threadIdx.x;
    const int s   = blockIdx.x;

    // ---- per-thread feature-slot metadata (registers only) ----
    int   sc1[NSLOTS], sc2[NSLOTS], sdv[NSLOTS];
    float ssc[NSLOTS];
    float facc[NSLOTS][NSP];
#pragma unroll
    for (int k = 0; k < NSLOTS; ++k) {
        int f = tid + k * NTHREADS;
        sc1[k] = 0; sc2[k] = 0; sdv[k] = 0; ssc[k] = 1.f;
#pragma unroll
        for (int sp = 0; sp < NSP; ++sp) facc[k][sp] = 0.f;
        if (f < NPAIR) {
            int l, q, base, coff;
            if (f < 528)       { l = 0; q = 32; base = 0;    coff = 0;   }
            else if (f < 828)  { l = 1; q = 24; base = 528;  coff = 32;  }
            else if (f < 1038) { l = 2; q = 20; base = 828;  coff = 104; }
            else               { l = 3; q = 16; base = 1038; coff = 204; }
            int rem = f - base, i1 = 0;
            while (rem >= q - i1) { rem -= q - i1; ++i1; }   // triangular inversion
            int i2 = i1 + rem;
            int d  = 2 * l + 1;
            sc1[k] = coff + i1 * d;
            sc2[k] = coff + i2 * d;
            sdv[k] = d;
            const float invsq[4] = {1.0f, 0.5773502691896258f,
                                    0.4472135954999579f, 0.3779644730092272f};
            ssc[k] = invsq[l] * ((i1 == i2) ? 1.0f : 1.4142135623730951f);
        }
    }

    const int a0 = g_start[s];
    const int a1 = g_start[s + 1];

    for (int base = a0; base < a1; base += TILE) {
        const int nt = min(TILE, a1 - base);
        __syncthreads();   // previous tile's compute done before overwriting tileS
        // stage coefficient tile: coalesced along atoms for each coeff row
        for (int idx = tid; idx < NCOEF * TILE; idx += NTHREADS) {
            int c  = idx >> 5;
            int ta = idx & (TILE - 1);
            if (ta < nt) {
                const float* p; int r;
                if (c < 32)       { p = sph0; r = c;       }
                else if (c < 104) { p = sph1; r = c - 32;  }
                else if (c < 204) { p = sph2; r = c - 104; }
                else              { p = sph3; r = c - 204; }
                tileS[c * STRIDE + ta] = p[(long)r * n_atoms + base + ta];
            }
        }
        if (tid < TILE) ssp[tid] = (tid < nt) ? species[base + tid] : 0;
        __syncthreads();

#pragma unroll
        for (int k = 0; k < NSLOTS; ++k) {
            int f = tid + k * NTHREADS;
            if (f < NPAIR) {
                const float* r1 = tileS + sc1[k] * STRIDE;
                const float* r2 = tileS + sc2[k] * STRIDE;
                switch (sdv[k]) {
                    case 1:  accum_pairs<1>(r1, r2, ssp, nt, facc[k]); break;
                    case 3:  accum_pairs<3>(r1, r2, ssp, nt, facc[k]); break;
                    case 5:  accum_pairs<5>(r1, r2, ssp, nt, facc[k]); break;
                    default: accum_pairs<7>(r1, r2, ssp, nt, facc[k]); break;
                }
            } else if (f < NPAIR + NRAD) {
                int j = f - NPAIR;
                for (int ta = 0; ta < nt; ++ta) {
                    float v = radial[(long)(base + ta) * NRAD + j];
                    int sp = ssp[ta];
                    facc[k][0] += (sp == 0) ? v : 0.f;
                    facc[k][1] += (sp == 1) ? v : 0.f;
                    facc[k][2] += (sp == 2) ? v : 0.f;
                    facc[k][3] += (sp == 3) ? v : 0.f;
                }
            } else if (f == NPAIR + NRAD) {
                for (int ta = 0; ta < nt; ++ta) {
                    float v = comp[base + ta];
                    int sp = ssp[ta];
                    facc[k][0] += (sp == 0) ? v : 0.f;
                    facc[k][1] += (sp == 1) ? v : 0.f;
                    facc[k][2] += (sp == 2) ? v : 0.f;
                    facc[k][3] += (sp == 3) ? v : 0.f;
                }
            }
        }
    }

    // ---- write: each (feature, species) owned by exactly one thread ----
    const int ncols = NSP * NFEAT;   // 4956
#pragma unroll
    for (int k = 0; k < NSLOTS; ++k) {
        int f = tid + k * NTHREADS;
        if (f >= NFEAT) continue;
#pragma unroll
        for (int sp = 0; sp < NSP; ++sp) {
            int col;
            if (f < NPAIR)             col = NSP + NSP * NRAD + sp * NPAIR + f;  // B2 block
            else if (f < NPAIR + NRAD) col = NSP + sp * NRAD + (f - NPAIR);      // radial block
            else                       col = sp;                                 // composition
            out[s * ncols + col] = ssc[k] * facc[k][sp];
        }
    }
}

extern "C" void kernel_launch(void* const* d_in, const int* in_sizes, int n_in,
                              void* d_out, int out_size) {
    const float* comp    = (const float*)d_in[0];
    const float* radial  = (const float*)d_in[1];
    const float* sph0    = (const float*)d_in[2];
    const float* sph1    = (const float*)d_in[3];
    const float* sph2    = (const float*)d_in[4];
    const float* sph3    = (const float*)d_in[5];
    const int*   sidx    = (const int*)d_in[6];
    const int*   species = (const int*)d_in[7];
    float*       out     = (float*)d_out;

    int n_atoms = in_sizes[0];                 // composition_features is [n_atoms, 1]
    int S       = out_size / (NSP * NFEAT);    // 4956 cols per structure
    if (S > MAXS) S = MAXS;

    bounds_kernel<<<(n_atoms + 255) / 256, 256>>>(sidx, n_atoms, S);
    le_ace_kernel<<<S, NTHREADS>>>(comp, radial, sph0, sph1, sph2, sph3,
                                   species, out, n_atoms);
}